// round 6
// baseline (speedup 1.0000x reference)
#include <cuda_runtime.h>

#define D    32
#define KN   26
#define NMAX 125000
#define XSTR 36

// kernel A / prepass config
#define A_CPW 4
#define A_WPB 12
#define A_TPB (A_WPB * 32)
// kernel B config
#define B_CPW 8
#define B_WPB 8
#define B_TPB (B_WPB * 32)

__device__ float  g_msg[NMAX * D];           // tanh(state @ W_msg + b_msg)
__device__ float4 g_X[(NMAX + 64) * D];      // (cur, a0, fm, a2) per (cell, i)
__device__ float4 g_Wt[NMAX + 64];           // (w0, w1, w2, -) gate weights per cell

__device__ __forceinline__ float tanh_fast(float x) {
    float y;
    asm("tanh.approx.f32 %0, %1;" : "=f"(y) : "f"(x));
    return y;
}

// ---------------------------------------------------------------------------
// Prepass: g_msg[cell] = tanh(states[cell] @ W_msg + b_msg)
// ---------------------------------------------------------------------------
__global__ __launch_bounds__(A_TPB) void msg_prepass(
    int n, const float* __restrict__ states,
    const float* __restrict__ W_msg, const float* __restrict__ b_msg)
{
    __shared__ float sx[A_WPB][A_CPW * XSTR];
    const int lane = threadIdx.x & 31, warp = threadIdx.x >> 5;
    const int base = (blockIdx.x * A_WPB + warp) * A_CPW;
    if (base >= n) return;

    float wm[D];
#pragma unroll
    for (int i = 0; i < D; i++) wm[i] = __ldg(W_msg + i * D + lane);
    const float bm = __ldg(b_msg + lane);

    float* xb = sx[warp];
#pragma unroll
    for (int c = 0; c < A_CPW; c++) {
        int cell = base + c;
        xb[c * XSTR + lane] = (cell < n) ? states[cell * D + lane] : 0.f;
    }
    __syncwarp();
#pragma unroll
    for (int c = 0; c < A_CPW; c++) {
        int cell = base + c;
        float m = bm;
#pragma unroll
        for (int i8 = 0; i8 < 8; i8++) {
            float4 xv = *reinterpret_cast<const float4*>(xb + c * XSTR + 4 * i8);
            m = fmaf(xv.x, wm[4 * i8 + 0], m);
            m = fmaf(xv.y, wm[4 * i8 + 1], m);
            m = fmaf(xv.z, wm[4 * i8 + 2], m);
            m = fmaf(xv.w, wm[4 * i8 + 3], m);
        }
        if (cell < n) g_msg[cell * D + lane] = tanh_fast(m);
    }
}

// ---------------------------------------------------------------------------
// Kernel A: gather + tier means + FULL gate softmax; writes g_X / g_Wt
// ---------------------------------------------------------------------------
__global__ __launch_bounds__(A_TPB) void gather_gate(
    int n, const float* __restrict__ states,
    const int* __restrict__ nbr, const int* __restrict__ tiers,
    const float* __restrict__ W_gate, const float* __restrict__ b_gate)
{
    const int lane = threadIdx.x & 31, warp = threadIdx.x >> 5;
    const int base = (blockIdx.x * A_WPB + warp) * A_CPW;
    if (base >= n) return;
    const unsigned FULL = 0xffffffffu;

    const char* sb = (const char*)states + lane * 4;
    const char* mb = (const char*)g_msg  + lane * 4;

    float wg[4][3];
#pragma unroll
    for (int s = 0; s < 4; s++)
#pragma unroll
        for (int e = 0; e < 3; e++)
            wg[s][e] = __ldg(W_gate + (s * D + lane) * 3 + e);
    const float bg0 = __ldg(b_gate + 0), bg1 = __ldg(b_gate + 1), bg2 = __ldg(b_gate + 2);

#pragma unroll
    for (int c = 0; c < A_CPW; c++) {
        const int cell = base + c;
        const bool act = (cell < n);

        float cu = act ? states[cell * D + lane] : 0.f;
        int mypk = 3, myt = 3;
        if (act && lane < KN) {
            int idx = __ldg(nbr   + cell * KN + lane);
            myt     = __ldg(tiers + cell * KN + lane);
            mypk    = idx * 128 + myt;
        }
        const unsigned mask0 = __ballot_sync(FULL, myt == 0);
        const unsigned mask1 = __ballot_sync(FULL, myt == 1);
        const float n0 = (float)__popc(mask0);
        const float n1 = (float)__popc(mask1);
        const float n2 = act ? (float)(KN) - n0 - n1 : 0.f;

        float a0 = 0.f, a1 = 0.f, tot = 0.f, fm = 0.f;
#pragma unroll
        for (int k = 0; k < KN; k++) {
            const int pk  = __shfl_sync(FULL, mypk, k);       // warp-uniform
            const int t   = pk & 3;
            const long off = (long)(pk & ~127);
            const float v = __ldg((const float*)(sb + off));
            float mv;
            asm("{ .reg .pred p;\n\t"
                "  setp.eq.s32 p, %1, 1;\n\t"
                "  mov.f32 %0, 0f00000000;\n\t"
                "  @p ld.global.nc.f32 %0, [%2];\n\t"
                "}" : "=f"(mv) : "r"(t), "l"(mb + off));
            tot += v;
            a0  += (t == 0) ? v : 0.f;
            a1  += (t == 1) ? v : 0.f;
            fm  += mv;
        }
        float a2 = tot - a0 - a1;

        a0 = __fdividef(a0, fmaxf(n0, 1.f));
        a1 = __fdividef(a1, fmaxf(n1, 1.f));
        a2 = __fdividef(a2, fmaxf(n2, 1.f));
        fm = __fdividef(fm, fmaxf(n1, 1.f));

        if (act)
            g_X[(size_t)cell * D + lane] = make_float4(cu, a0, fm, a2);

        // full gate here (needs cur, a0, a1, a2 only)
        float p0 = cu * wg[0][0] + a0 * wg[1][0] + a1 * wg[2][0] + a2 * wg[3][0];
        float p1 = cu * wg[0][1] + a0 * wg[1][1] + a1 * wg[2][1] + a2 * wg[3][1];
        float p2 = cu * wg[0][2] + a0 * wg[1][2] + a1 * wg[2][2] + a2 * wg[3][2];
#pragma unroll
        for (int o = 16; o > 0; o >>= 1) {
            p0 += __shfl_xor_sync(FULL, p0, o);
            p1 += __shfl_xor_sync(FULL, p1, o);
            p2 += __shfl_xor_sync(FULL, p2, o);
        }
        if (act && lane == 0) {
            const float g0 = p0 + bg0, g1 = p1 + bg1, g2 = p2 + bg2;
            const float mx = fmaxf(g0, fmaxf(g1, g2));
            const float e0 = __expf(g0 - mx), e1 = __expf(g1 - mx), e2 = __expf(g2 - mx);
            const float inv = __fdividef(1.f, e0 + e1 + e2);
            g_Wt[cell] = make_float4(e0 * inv, e1 * inv, e2 * inv, 0.f);
        }
    }
}

// ---------------------------------------------------------------------------
// Kernel B: experts; 8 cells/warp; inputs via direct __ldg broadcasts
// ---------------------------------------------------------------------------
__global__ __launch_bounds__(B_TPB, 4) void experts(
    int n, const float* __restrict__ states,
    const float* __restrict__ W_loc, const float* __restrict__ b_loc,
    const float* __restrict__ W_fun, const float* __restrict__ b_fun,
    const float* __restrict__ W_cnf, const float* __restrict__ b_cnf,
    float* __restrict__ out)
{
    __shared__ float4 sWloc4[16 * 32];
    __shared__ float4 sWfun4[16 * 32];
    __shared__ float4 sWcnf4[16 * 32];
    __shared__ float  sX[B_WPB][B_CPW * XSTR];

    for (int e = threadIdx.x; e < 16 * 32; e += B_TPB) {
        int i = (e >> 5) * 4, j = e & 31;
        sWloc4[e] = make_float4(W_loc[i * 32 + j], W_loc[(i + 1) * 32 + j],
                                W_loc[(i + 2) * 32 + j], W_loc[(i + 3) * 32 + j]);
        sWfun4[e] = make_float4(W_fun[i * 32 + j], W_fun[(i + 1) * 32 + j],
                                W_fun[(i + 2) * 32 + j], W_fun[(i + 3) * 32 + j]);
        sWcnf4[e] = make_float4(W_cnf[i * 32 + j], W_cnf[(i + 1) * 32 + j],
                                W_cnf[(i + 2) * 32 + j], W_cnf[(i + 3) * 32 + j]);
    }
    __syncthreads();

    const int lane = threadIdx.x & 31, warp = threadIdx.x >> 5;
    const int base = (blockIdx.x * B_WPB + warp) * B_CPW;
    if (base >= n) return;

    const float4* gx = g_X + (size_t)base * D;   // consecutive cells; padded array

    // ---- fused pass: accL, accF, h2 for 8 cells ----
    float accL[B_CPW], accF[B_CPW], h2[B_CPW];
    {
        const float bl = __ldg(b_loc + lane);
        const float bf = __ldg(b_fun + lane);
        const float bc = __ldg(b_cnf + lane);
#pragma unroll
        for (int c = 0; c < B_CPW; c++) { accL[c] = bl; accF[c] = bf; h2[c] = bc; }
    }

#pragma unroll
    for (int i4 = 0; i4 < 8; i4++) {
        const float4 wlT = sWloc4[i4 * 32 + lane];
        const float4 wlB = sWloc4[(i4 + 8) * 32 + lane];
        const float4 wfT = sWfun4[i4 * 32 + lane];
        const float4 wfB = sWfun4[(i4 + 8) * 32 + lane];
        const float4 wcB = sWcnf4[(i4 + 8) * 32 + lane];
#pragma unroll
        for (int c = 0; c < B_CPW; c++) {
            const float4* p = gx + c * D + 4 * i4;
            const float4 x0 = __ldg(p + 0);        // 16B broadcast, L1-cached
            const float4 x1 = __ldg(p + 1);
            const float4 x2 = __ldg(p + 2);
            const float4 x3 = __ldg(p + 3);
            accL[c] = fmaf(x0.x, wlT.x, fmaf(x0.y, wlB.x, accL[c]));
            accL[c] = fmaf(x1.x, wlT.y, fmaf(x1.y, wlB.y, accL[c]));
            accL[c] = fmaf(x2.x, wlT.z, fmaf(x2.y, wlB.z, accL[c]));
            accL[c] = fmaf(x3.x, wlT.w, fmaf(x3.y, wlB.w, accL[c]));
            accF[c] = fmaf(x0.x, wfT.x, fmaf(x0.z, wfB.x, accF[c]));
            accF[c] = fmaf(x1.x, wfT.y, fmaf(x1.z, wfB.y, accF[c]));
            accF[c] = fmaf(x2.x, wfT.z, fmaf(x2.z, wfB.z, accF[c]));
            accF[c] = fmaf(x3.x, wfT.w, fmaf(x3.z, wfB.w, accF[c]));
            h2[c]   = fmaf(x0.w, wcB.x, h2[c]);
            h2[c]   = fmaf(x1.w, wcB.y, h2[c]);
            h2[c]   = fmaf(x2.w, wcB.z, h2[c]);
            h2[c]   = fmaf(x3.w, wcB.w, h2[c]);
        }
    }

    // ---- partial combine (frees accL/accF), init CNF state ----
    float opart[B_CPW], gw2[B_CPW], x[B_CPW];
#pragma unroll
    for (int c = 0; c < B_CPW; c++) {
        const float4 gwv = __ldg(g_Wt + base + c);          // padded, zero-init
        opart[c] = gwv.x * tanh_fast(accL[c]) + gwv.y * tanh_fast(accF[c]);
        gw2[c]   = gwv.z;
        const int cell = min(base + c, n - 1);
        x[c] = states[(size_t)cell * D + lane];
    }

    // ---- CNF: 3 explicit-Euler steps (h2 reused) ----
    float* xxb = sX[warp];
#pragma unroll
    for (int s = 0; s < 3; s++) {
        __syncwarp();
#pragma unroll
        for (int c = 0; c < B_CPW; c++) xxb[c * XSTR + lane] = x[c];
        __syncwarp();
        float acc[B_CPW];
#pragma unroll
        for (int c = 0; c < B_CPW; c++) acc[c] = h2[c];
#pragma unroll
        for (int i4 = 0; i4 < 8; i4++) {
            const float4 w = sWcnf4[i4 * 32 + lane];
#pragma unroll
            for (int c = 0; c < B_CPW; c++) {
                const float4 xv = *reinterpret_cast<const float4*>(xxb + c * XSTR + 4 * i4);
                acc[c] = fmaf(xv.x, w.x, fmaf(xv.y, w.y, fmaf(xv.z, w.z, fmaf(xv.w, w.w, acc[c]))));
            }
        }
#pragma unroll
        for (int c = 0; c < B_CPW; c++)
            x[c] = fmaf(1.0f / 3.0f, tanh_fast(acc[c]), x[c]);
    }

    // ---- final combine + store ----
#pragma unroll
    for (int c = 0; c < B_CPW; c++) {
        const int cell = base + c;
        if (cell < n)
            out[(size_t)cell * D + lane] = opart[c] + gw2[c] * x[c];
    }
}

extern "C" void kernel_launch(void* const* d_in, const int* in_sizes, int n_in,
                              void* d_out, int out_size) {
    const float* states = (const float*)d_in[0];
    const int*   nbr    = (const int*)  d_in[1];
    const int*   tiers  = (const int*)  d_in[2];
    const float* W_loc  = (const float*)d_in[3];
    const float* b_loc  = (const float*)d_in[4];
    const float* W_msg  = (const float*)d_in[5];
    const float* b_msg  = (const float*)d_in[6];
    const float* W_fun  = (const float*)d_in[7];
    const float* b_fun  = (const float*)d_in[8];
    const float* W_cnf  = (const float*)d_in[9];
    const float* b_cnf  = (const float*)d_in[10];
    const float* W_gate = (const float*)d_in[11];
    const float* b_gate = (const float*)d_in[12];
    float* out = (float*)d_out;

    const int n = in_sizes[0] / D;
    const int blocksA = (n + A_WPB * A_CPW - 1) / (A_WPB * A_CPW);
    const int blocksB = (n + B_WPB * B_CPW - 1) / (B_WPB * B_CPW);

    msg_prepass<<<blocksA, A_TPB>>>(n, states, W_msg, b_msg);
    gather_gate<<<blocksA, A_TPB>>>(n, states, nbr, tiers, W_gate, b_gate);
    experts<<<blocksB, B_TPB>>>(n, states, W_loc, b_loc, W_fun, b_fun,
                                W_cnf, b_cnf, out);
}

// round 7
// speedup vs baseline: 1.3509x; 1.3509x over previous
#include <cuda_runtime.h>

#define D    32
#define KN   26
#define CPW  4               // cells per warp
#define WPB  12              // warps per block
#define TPB  (WPB * 32)
#define NMAX 125000
#define XSTR 36              // x staging row stride (16B-aligned float4 reads)

__device__ float g_msg[NMAX * D];   // precomputed tanh(state @ W_msg + b_msg)

__device__ __forceinline__ float tanh_fast(float x) {
    float y;
    asm("tanh.approx.f32 %0, %1;" : "=f"(y) : "f"(x));
    return y;
}

// ---------------------------------------------------------------------------
// Prepass: g_msg[cell] = tanh(states[cell] @ W_msg + b_msg)   (per SOURCE cell)
// ---------------------------------------------------------------------------
__global__ __launch_bounds__(TPB) void msg_prepass(
    int n, const float* __restrict__ states,
    const float* __restrict__ W_msg, const float* __restrict__ b_msg)
{
    __shared__ float sx[WPB][CPW * XSTR];
    const int lane = threadIdx.x & 31, warp = threadIdx.x >> 5;
    const int base = (blockIdx.x * WPB + warp) * CPW;
    if (base >= n) return;

    float wm[D];                                   // lane holds W_msg[:, lane]
#pragma unroll
    for (int i = 0; i < D; i++) wm[i] = __ldg(W_msg + i * D + lane);
    const float bm = __ldg(b_msg + lane);

    float* xb = sx[warp];
#pragma unroll
    for (int c = 0; c < CPW; c++) {
        int cell = base + c;
        xb[c * XSTR + lane] = (cell < n) ? states[cell * D + lane] : 0.f;
    }
    __syncwarp();
#pragma unroll
    for (int c = 0; c < CPW; c++) {
        int cell = base + c;
        float m = bm;
#pragma unroll
        for (int i8 = 0; i8 < 8; i8++) {
            float4 xv = *reinterpret_cast<const float4*>(xb + c * XSTR + 4 * i8);
            m = fmaf(xv.x, wm[4 * i8 + 0], m);
            m = fmaf(xv.y, wm[4 * i8 + 1], m);
            m = fmaf(xv.z, wm[4 * i8 + 2], m);
            m = fmaf(xv.w, wm[4 * i8 + 3], m);
        }
        if (cell < n) g_msg[cell * D + lane] = tanh_fast(m);
    }
}

// ---------------------------------------------------------------------------
// Main kernel: 48 warps/SM, branchless gather (.cg), smem gate weights
// ---------------------------------------------------------------------------
__global__ __launch_bounds__(TPB, 4) void moe_main(
    int n,
    const float* __restrict__ states,
    const int*   __restrict__ nbr,
    const int*   __restrict__ tiers,
    const float* __restrict__ W_loc,  const float* __restrict__ b_loc,
    const float* __restrict__ W_fun,  const float* __restrict__ b_fun,
    const float* __restrict__ W_cnf,  const float* __restrict__ b_cnf,
    const float* __restrict__ W_gate, const float* __restrict__ b_gate,
    float* __restrict__ out)
{
    extern __shared__ char smem[];
    float4* sWloc4 = reinterpret_cast<float4*>(smem);                 // 16*32 float4
    float4* sWfun4 = sWloc4 + 16 * 32;
    float4* sWcnf4 = sWfun4 + 16 * 32;
    float4* sInAll = sWcnf4 + 16 * 32;                                // WPB*CPW*32 float4
    float*  sXAll  = reinterpret_cast<float*>(sInAll + WPB * CPW * D); // WPB*CPW*XSTR
    float*  sWg    = sXAll + WPB * CPW * XSTR;                         // 128*3 gate weights

    // stage weights packed over i (4 coalesced LDG.32 -> 1 STS.128)
    for (int e = threadIdx.x; e < 16 * 32; e += TPB) {
        int i = (e >> 5) * 4, j = e & 31;
        sWloc4[e] = make_float4(W_loc[i * 32 + j], W_loc[(i + 1) * 32 + j],
                                W_loc[(i + 2) * 32 + j], W_loc[(i + 3) * 32 + j]);
        sWfun4[e] = make_float4(W_fun[i * 32 + j], W_fun[(i + 1) * 32 + j],
                                W_fun[(i + 2) * 32 + j], W_fun[(i + 3) * 32 + j]);
        sWcnf4[e] = make_float4(W_cnf[i * 32 + j], W_cnf[(i + 1) * 32 + j],
                                W_cnf[(i + 2) * 32 + j], W_cnf[(i + 3) * 32 + j]);
    }
    for (int e = threadIdx.x; e < 128 * 3; e += TPB) sWg[e] = W_gate[e];
    __syncthreads();

    const int lane = threadIdx.x & 31, warp = threadIdx.x >> 5;
    const int base = (blockIdx.x * WPB + warp) * CPW;
    if (base >= n) return;
    const unsigned FULL = 0xffffffffu;

    const char* sb = (const char*)states + lane * 4;   // lane-offset byte bases
    const char* mb = (const char*)g_msg  + lane * 4;

    float4* inb = sInAll + warp * (CPW * D);
    float*  xxb = sXAll  + warp * (CPW * XSTR);
    float   A1[CPW];

    // ---- gather + tier means + message gather (branchless, L2-only loads) ----
#pragma unroll
    for (int c = 0; c < CPW; c++) {
        const int cell = base + c;
        const bool act = (cell < n);

        float cu = act ? states[cell * D + lane] : 0.f;
        int mypk = 3;                                  // tier 3 = inactive
        int myt  = 3;
        if (act && lane < KN) {
            int idx = __ldg(nbr   + cell * KN + lane);
            myt     = __ldg(tiers + cell * KN + lane);
            mypk    = idx * 128 + myt;                 // byte offset | tier
        }
        const unsigned mask0 = __ballot_sync(FULL, myt == 0);
        const unsigned mask1 = __ballot_sync(FULL, myt == 1);
        const float n0 = (float)__popc(mask0);
        const float n1 = (float)__popc(mask1);
        const float n2 = act ? (float)(KN) - n0 - n1 : 0.f;

        float a0 = 0.f, a1 = 0.f, tot = 0.f, fm = 0.f;
#pragma unroll
        for (int k = 0; k < KN; k++) {
            const int pk  = __shfl_sync(FULL, mypk, k);           // warp-uniform
            const int t   = pk & 3;
            const long off = (long)(pk & ~127);
            const float v = __ldcg((const float*)(sb + off));     // L2-only (random)
            // guaranteed-predicated L2-only msg load (tier-1 neighbors only)
            float mv;
            asm("{ .reg .pred p;\n\t"
                "  setp.eq.s32 p, %1, 1;\n\t"
                "  mov.f32 %0, 0f00000000;\n\t"
                "  @p ld.global.cg.f32 %0, [%2];\n\t"
                "}" : "=f"(mv) : "r"(t), "l"(mb + off));
            tot += v;
            a0  += (t == 0) ? v : 0.f;                            // predicated
            a1  += (t == 1) ? v : 0.f;
            fm  += mv;
        }
        float a2 = tot - a0 - a1;

        a0 = __fdividef(a0, fmaxf(n0, 1.f));
        a1 = __fdividef(a1, fmaxf(n1, 1.f));
        a2 = __fdividef(a2, fmaxf(n2, 1.f));
        fm = __fdividef(fm, fmaxf(n1, 1.f));

        A1[c] = a1;
        inb[c * D + lane] = make_float4(cu, a0, fm, a2);          // STS.128
    }
    __syncwarp();

    // ---- fused pass: loc, fun, CNF conditioning half (h2); packed weights ----
    float accL[CPW], accF[CPW], h2[CPW];
    {
        const float bl = __ldg(b_loc + lane);
        const float bf = __ldg(b_fun + lane);
        const float bc = __ldg(b_cnf + lane);
#pragma unroll
        for (int c = 0; c < CPW; c++) { accL[c] = bl; accF[c] = bf; h2[c] = bc; }
    }

#pragma unroll
    for (int i4 = 0; i4 < 8; i4++) {
        const float4 wlT = sWloc4[i4 * 32 + lane];        // rows 4i4..4i4+3 (top)
        const float4 wlB = sWloc4[(i4 + 8) * 32 + lane];  // rows 32+...
        const float4 wfT = sWfun4[i4 * 32 + lane];
        const float4 wfB = sWfun4[(i4 + 8) * 32 + lane];
        const float4 wcB = sWcnf4[(i4 + 8) * 32 + lane];
#pragma unroll
        for (int c = 0; c < CPW; c++) {
            const float4 x0 = inb[c * D + 4 * i4 + 0];    // broadcast LDS.128
            const float4 x1 = inb[c * D + 4 * i4 + 1];
            const float4 x2 = inb[c * D + 4 * i4 + 2];
            const float4 x3 = inb[c * D + 4 * i4 + 3];
            accL[c] = fmaf(x0.x, wlT.x, fmaf(x0.y, wlB.x, accL[c]));
            accL[c] = fmaf(x1.x, wlT.y, fmaf(x1.y, wlB.y, accL[c]));
            accL[c] = fmaf(x2.x, wlT.z, fmaf(x2.y, wlB.z, accL[c]));
            accL[c] = fmaf(x3.x, wlT.w, fmaf(x3.y, wlB.w, accL[c]));
            accF[c] = fmaf(x0.x, wfT.x, fmaf(x0.z, wfB.x, accF[c]));
            accF[c] = fmaf(x1.x, wfT.y, fmaf(x1.z, wfB.y, accF[c]));
            accF[c] = fmaf(x2.x, wfT.z, fmaf(x2.z, wfB.z, accF[c]));
            accF[c] = fmaf(x3.x, wfT.w, fmaf(x3.z, wfB.w, accF[c]));
            h2[c]   = fmaf(x0.w, wcB.x, h2[c]);
            h2[c]   = fmaf(x1.w, wcB.y, h2[c]);
            h2[c]   = fmaf(x2.w, wcB.z, h2[c]);
            h2[c]   = fmaf(x3.w, wcB.w, h2[c]);
        }
    }
    float loc[CPW], fun[CPW], x[CPW];
#pragma unroll
    for (int c = 0; c < CPW; c++) {
        loc[c] = tanh_fast(accL[c]);
        fun[c] = tanh_fast(accF[c]);
        x[c]   = inb[c * D + lane].x;               // cur re-read
    }

    // ---- CNF: 3 explicit-Euler steps, top half only (h2 reused) ----
#pragma unroll
    for (int s = 0; s < 3; s++) {
        __syncwarp();
#pragma unroll
        for (int c = 0; c < CPW; c++) xxb[c * XSTR + lane] = x[c];
        __syncwarp();
        float acc[CPW];
#pragma unroll
        for (int c = 0; c < CPW; c++) acc[c] = h2[c];
#pragma unroll
        for (int i4 = 0; i4 < 8; i4++) {
            const float4 w = sWcnf4[i4 * 32 + lane];              // top rows
#pragma unroll
            for (int c = 0; c < CPW; c++) {
                const float4 xv = *reinterpret_cast<const float4*>(xxb + c * XSTR + 4 * i4);
                acc[c] = fmaf(xv.x, w.x, fmaf(xv.y, w.y, fmaf(xv.z, w.z, fmaf(xv.w, w.w, acc[c]))));
            }
        }
#pragma unroll
        for (int c = 0; c < CPW; c++)
            x[c] = fmaf(1.0f / 3.0f, tanh_fast(acc[c]), x[c]);
    }

    // ---- gate: weights from smem (stride-3 = conflict-free) + butterfly ----
    float wg[4][3];
#pragma unroll
    for (int s = 0; s < 4; s++)
#pragma unroll
        for (int e = 0; e < 3; e++)
            wg[s][e] = sWg[(s * D + lane) * 3 + e];
    const float bg0 = __ldg(b_gate + 0), bg1 = __ldg(b_gate + 1), bg2 = __ldg(b_gate + 2);

#pragma unroll
    for (int c = 0; c < CPW; c++) {
        const float4 gi = inb[c * D + lane];        // (cur, a0, fm, a2) per lane
        float p0 = gi.x * wg[0][0] + gi.y * wg[1][0] + A1[c] * wg[2][0] + gi.w * wg[3][0];
        float p1 = gi.x * wg[0][1] + gi.y * wg[1][1] + A1[c] * wg[2][1] + gi.w * wg[3][1];
        float p2 = gi.x * wg[0][2] + gi.y * wg[1][2] + A1[c] * wg[2][2] + gi.w * wg[3][2];
#pragma unroll
        for (int o = 16; o > 0; o >>= 1) {
            p0 += __shfl_xor_sync(FULL, p0, o);
            p1 += __shfl_xor_sync(FULL, p1, o);
            p2 += __shfl_xor_sync(FULL, p2, o);
        }
        const float g0 = p0 + bg0, g1 = p1 + bg1, g2 = p2 + bg2;
        const float mx = fmaxf(g0, fmaxf(g1, g2));
        const float e0 = __expf(g0 - mx), e1 = __expf(g1 - mx), e2 = __expf(g2 - mx);
        const float inv = __fdividef(1.f, e0 + e1 + e2);

        const int cell = base + c;
        if (cell < n)
            out[cell * D + lane] = (e0 * loc[c] + e1 * fun[c] + e2 * x[c]) * inv;
    }
}

extern "C" void kernel_launch(void* const* d_in, const int* in_sizes, int n_in,
                              void* d_out, int out_size) {
    const float* states = (const float*)d_in[0];
    const int*   nbr    = (const int*)  d_in[1];
    const int*   tiers  = (const int*)  d_in[2];
    const float* W_loc  = (const float*)d_in[3];
    const float* b_loc  = (const float*)d_in[4];
    const float* W_msg  = (const float*)d_in[5];
    const float* b_msg  = (const float*)d_in[6];
    const float* W_fun  = (const float*)d_in[7];
    const float* b_fun  = (const float*)d_in[8];
    const float* W_cnf  = (const float*)d_in[9];
    const float* b_cnf  = (const float*)d_in[10];
    const float* W_gate = (const float*)d_in[11];
    const float* b_gate = (const float*)d_in[12];
    float* out = (float*)d_out;

    const int n = in_sizes[0] / D;
    const int blocks = (n + WPB * CPW - 1) / (WPB * CPW);

    // dynamic smem: 3 weight arrays + input staging + CNF x staging + gate W
    const int smem_bytes = (3 * 16 * 32) * (int)sizeof(float4)
                         + (WPB * CPW * D) * (int)sizeof(float4)
                         + (WPB * CPW * XSTR) * (int)sizeof(float)
                         + (128 * 3) * (int)sizeof(float);
    static bool attr_set = false;
    if (!attr_set) {
        cudaFuncSetAttribute(moe_main, cudaFuncAttributeMaxDynamicSharedMemorySize, smem_bytes);
        attr_set = true;
    }

    msg_prepass<<<blocks, TPB>>>(n, states, W_msg, b_msg);
    moe_main<<<blocks, TPB, smem_bytes>>>(n, states, nbr, tiers,
                                          W_loc, b_loc, W_fun, b_fun,
                                          W_cnf, b_cnf, W_gate, b_gate, out);
}

// round 8
// speedup vs baseline: 1.3852x; 1.0254x over previous
#include <cuda_runtime.h>

#define D    32
#define KN   26
#define CPW  4               // cells per warp
#define WPB  12              // warps per block
#define TPB  (WPB * 32)
#define NMAX 125000
#define XSTR 36              // x staging row stride (16B-aligned float4 reads)

__device__ float g_msg[NMAX * D];   // precomputed tanh(state @ W_msg + b_msg)

__device__ __forceinline__ float tanh_fast(float x) {
    float y;
    asm("tanh.approx.f32 %0, %1;" : "=f"(y) : "f"(x));
    return y;
}

// ---------------------------------------------------------------------------
// Prepass: g_msg[cell] = tanh(states[cell] @ W_msg + b_msg)   (per SOURCE cell)
// ---------------------------------------------------------------------------
__global__ __launch_bounds__(TPB) void msg_prepass(
    int n, const float* __restrict__ states,
    const float* __restrict__ W_msg, const float* __restrict__ b_msg)
{
    __shared__ float sx[WPB][CPW * XSTR];
    const int lane = threadIdx.x & 31, warp = threadIdx.x >> 5;
    const int base = (blockIdx.x * WPB + warp) * CPW;
    if (base >= n) return;

    float wm[D];                                   // lane holds W_msg[:, lane]
#pragma unroll
    for (int i = 0; i < D; i++) wm[i] = __ldg(W_msg + i * D + lane);
    const float bm = __ldg(b_msg + lane);

    float* xb = sx[warp];
#pragma unroll
    for (int c = 0; c < CPW; c++) {
        int cell = base + c;
        xb[c * XSTR + lane] = (cell < n) ? states[cell * D + lane] : 0.f;
    }
    __syncwarp();
#pragma unroll
    for (int c = 0; c < CPW; c++) {
        int cell = base + c;
        float m = bm;
#pragma unroll
        for (int i8 = 0; i8 < 8; i8++) {
            float4 xv = *reinterpret_cast<const float4*>(xb + c * XSTR + 4 * i8);
            m = fmaf(xv.x, wm[4 * i8 + 0], m);
            m = fmaf(xv.y, wm[4 * i8 + 1], m);
            m = fmaf(xv.z, wm[4 * i8 + 2], m);
            m = fmaf(xv.w, wm[4 * i8 + 3], m);
        }
        if (cell < n) g_msg[cell * D + lane] = tanh_fast(m);
    }
}

// ---------------------------------------------------------------------------
// Main kernel: 48 warps/SM, branchless gather w/ L2-only loads, LDG gate
// ---------------------------------------------------------------------------
__global__ __launch_bounds__(TPB, 4) void moe_main(
    int n,
    const float* __restrict__ states,
    const int*   __restrict__ nbr,
    const int*   __restrict__ tiers,
    const float* __restrict__ W_loc,  const float* __restrict__ b_loc,
    const float* __restrict__ W_fun,  const float* __restrict__ b_fun,
    const float* __restrict__ W_cnf,  const float* __restrict__ b_cnf,
    const float* __restrict__ W_gate, const float* __restrict__ b_gate,
    float* __restrict__ out)
{
    extern __shared__ char smem[];
    float4* sWloc4 = reinterpret_cast<float4*>(smem);                 // 16*32 float4
    float4* sWfun4 = sWloc4 + 16 * 32;
    float4* sWcnf4 = sWfun4 + 16 * 32;
    float4* sInAll = sWcnf4 + 16 * 32;                                // WPB*CPW*32 float4
    float*  sXAll  = reinterpret_cast<float*>(sInAll + WPB * CPW * D); // WPB*CPW*XSTR

    // stage weights packed over i (4 coalesced LDG.32 -> 1 STS.128)
    for (int e = threadIdx.x; e < 16 * 32; e += TPB) {
        int i = (e >> 5) * 4, j = e & 31;
        sWloc4[e] = make_float4(W_loc[i * 32 + j], W_loc[(i + 1) * 32 + j],
                                W_loc[(i + 2) * 32 + j], W_loc[(i + 3) * 32 + j]);
        sWfun4[e] = make_float4(W_fun[i * 32 + j], W_fun[(i + 1) * 32 + j],
                                W_fun[(i + 2) * 32 + j], W_fun[(i + 3) * 32 + j]);
        sWcnf4[e] = make_float4(W_cnf[i * 32 + j], W_cnf[(i + 1) * 32 + j],
                                W_cnf[(i + 2) * 32 + j], W_cnf[(i + 3) * 32 + j]);
    }
    __syncthreads();

    const int lane = threadIdx.x & 31, warp = threadIdx.x >> 5;
    const int base = (blockIdx.x * WPB + warp) * CPW;
    if (base >= n) return;
    const unsigned FULL = 0xffffffffu;

    const char* sb = (const char*)states + lane * 4;   // lane-offset byte bases
    const char* mb = (const char*)g_msg  + lane * 4;

    float4* inb = sInAll + warp * (CPW * D);
    float*  xxb = sXAll  + warp * (CPW * XSTR);
    float   A1[CPW];

    // ---- gather + tier means + message gather (branchless, L2-only loads) ----
#pragma unroll
    for (int c = 0; c < CPW; c++) {
        const int cell = base + c;
        const bool act = (cell < n);

        float cu = act ? states[cell * D + lane] : 0.f;
        int mypk = 3;                                  // tier 3 = inactive
        int myt  = 3;
        if (act && lane < KN) {
            int idx = __ldg(nbr   + cell * KN + lane);
            myt     = __ldg(tiers + cell * KN + lane);
            mypk    = idx * 128 + myt;                 // byte offset | tier
        }
        const unsigned mask0 = __ballot_sync(FULL, myt == 0);
        const unsigned mask1 = __ballot_sync(FULL, myt == 1);
        const float n0 = (float)__popc(mask0);
        const float n1 = (float)__popc(mask1);
        const float n2 = act ? (float)(KN) - n0 - n1 : 0.f;

        float a0 = 0.f, a1 = 0.f, tot = 0.f, fm = 0.f;
#pragma unroll
        for (int k = 0; k < KN; k++) {
            const int pk  = __shfl_sync(FULL, mypk, k);           // warp-uniform
            const int t   = pk & 3;
            const long off = (long)(pk & ~127);
            const float v = __ldcg((const float*)(sb + off));     // L2-only (random)
            // guaranteed-predicated L2-only msg load (tier-1 neighbors only)
            float mv;
            asm("{ .reg .pred p;\n\t"
                "  setp.eq.s32 p, %1, 1;\n\t"
                "  mov.f32 %0, 0f00000000;\n\t"
                "  @p ld.global.cg.f32 %0, [%2];\n\t"
                "}" : "=f"(mv) : "r"(t), "l"(mb + off));
            tot += v;
            a0  += (t == 0) ? v : 0.f;                            // predicated
            a1  += (t == 1) ? v : 0.f;
            fm  += mv;
        }
        float a2 = tot - a0 - a1;

        a0 = __fdividef(a0, fmaxf(n0, 1.f));
        a1 = __fdividef(a1, fmaxf(n1, 1.f));
        a2 = __fdividef(a2, fmaxf(n2, 1.f));
        fm = __fdividef(fm, fmaxf(n1, 1.f));

        A1[c] = a1;
        inb[c * D + lane] = make_float4(cu, a0, fm, a2);          // STS.128
    }
    __syncwarp();

    // ---- fused pass: loc, fun, CNF conditioning half (h2); packed weights ----
    float accL[CPW], accF[CPW], h2[CPW];
    {
        const float bl = __ldg(b_loc + lane);
        const float bf = __ldg(b_fun + lane);
        const float bc = __ldg(b_cnf + lane);
#pragma unroll
        for (int c = 0; c < CPW; c++) { accL[c] = bl; accF[c] = bf; h2[c] = bc; }
    }

#pragma unroll
    for (int i4 = 0; i4 < 8; i4++) {
        const float4 wlT = sWloc4[i4 * 32 + lane];        // rows 4i4..4i4+3 (top)
        const float4 wlB = sWloc4[(i4 + 8) * 32 + lane];  // rows 32+...
        const float4 wfT = sWfun4[i4 * 32 + lane];
        const float4 wfB = sWfun4[(i4 + 8) * 32 + lane];
        const float4 wcB = sWcnf4[(i4 + 8) * 32 + lane];
#pragma unroll
        for (int c = 0; c < CPW; c++) {
            const float4 x0 = inb[c * D + 4 * i4 + 0];    // broadcast LDS.128
            const float4 x1 = inb[c * D + 4 * i4 + 1];
            const float4 x2 = inb[c * D + 4 * i4 + 2];
            const float4 x3 = inb[c * D + 4 * i4 + 3];
            accL[c] = fmaf(x0.x, wlT.x, fmaf(x0.y, wlB.x, accL[c]));
            accL[c] = fmaf(x1.x, wlT.y, fmaf(x1.y, wlB.y, accL[c]));
            accL[c] = fmaf(x2.x, wlT.z, fmaf(x2.y, wlB.z, accL[c]));
            accL[c] = fmaf(x3.x, wlT.w, fmaf(x3.y, wlB.w, accL[c]));
            accF[c] = fmaf(x0.x, wfT.x, fmaf(x0.z, wfB.x, accF[c]));
            accF[c] = fmaf(x1.x, wfT.y, fmaf(x1.z, wfB.y, accF[c]));
            accF[c] = fmaf(x2.x, wfT.z, fmaf(x2.z, wfB.z, accF[c]));
            accF[c] = fmaf(x3.x, wfT.w, fmaf(x3.z, wfB.w, accF[c]));
            h2[c]   = fmaf(x0.w, wcB.x, h2[c]);
            h2[c]   = fmaf(x1.w, wcB.y, h2[c]);
            h2[c]   = fmaf(x2.w, wcB.z, h2[c]);
            h2[c]   = fmaf(x3.w, wcB.w, h2[c]);
        }
    }
    float loc[CPW], fun[CPW], x[CPW];
#pragma unroll
    for (int c = 0; c < CPW; c++) {
        loc[c] = tanh_fast(accL[c]);
        fun[c] = tanh_fast(accF[c]);
        x[c]   = inb[c * D + lane].x;               // cur re-read
    }

    // ---- CNF: 3 explicit-Euler steps, top half only (h2 reused) ----
#pragma unroll
    for (int s = 0; s < 3; s++) {
        __syncwarp();
#pragma unroll
        for (int c = 0; c < CPW; c++) xxb[c * XSTR + lane] = x[c];
        __syncwarp();
        float acc[CPW];
#pragma unroll
        for (int c = 0; c < CPW; c++) acc[c] = h2[c];
#pragma unroll
        for (int i4 = 0; i4 < 8; i4++) {
            const float4 w = sWcnf4[i4 * 32 + lane];              // top rows
#pragma unroll
            for (int c = 0; c < CPW; c++) {
                const float4 xv = *reinterpret_cast<const float4*>(xxb + c * XSTR + 4 * i4);
                acc[c] = fmaf(xv.x, w.x, fmaf(xv.y, w.y, fmaf(xv.z, w.z, fmaf(xv.w, w.w, acc[c]))));
            }
        }
#pragma unroll
        for (int c = 0; c < CPW; c++)
            x[c] = fmaf(1.0f / 3.0f, tanh_fast(acc[c]), x[c]);
    }

    // ---- gate: weights loaded here via LDG (short live range) + butterfly ----
    float wg[4][3];
#pragma unroll
    for (int s = 0; s < 4; s++)
#pragma unroll
        for (int e = 0; e < 3; e++)
            wg[s][e] = __ldg(W_gate + (s * D + lane) * 3 + e);
    const float bg0 = __ldg(b_gate + 0), bg1 = __ldg(b_gate + 1), bg2 = __ldg(b_gate + 2);

#pragma unroll
    for (int c = 0; c < CPW; c++) {
        const float4 gi = inb[c * D + lane];        // (cur, a0, fm, a2) per lane
        float p0 = gi.x * wg[0][0] + gi.y * wg[1][0] + A1[c] * wg[2][0] + gi.w * wg[3][0];
        float p1 = gi.x * wg[0][1] + gi.y * wg[1][1] + A1[c] * wg[2][1] + gi.w * wg[3][1];
        float p2 = gi.x * wg[0][2] + gi.y * wg[1][2] + A1[c] * wg[2][2] + gi.w * wg[3][2];
#pragma unroll
        for (int o = 16; o > 0; o >>= 1) {
            p0 += __shfl_xor_sync(FULL, p0, o);
            p1 += __shfl_xor_sync(FULL, p1, o);
            p2 += __shfl_xor_sync(FULL, p2, o);
        }
        const float g0 = p0 + bg0, g1 = p1 + bg1, g2 = p2 + bg2;
        const float mx = fmaxf(g0, fmaxf(g1, g2));
        const float e0 = __expf(g0 - mx), e1 = __expf(g1 - mx), e2 = __expf(g2 - mx);
        const float inv = __fdividef(1.f, e0 + e1 + e2);

        const int cell = base + c;
        if (cell < n)
            out[cell * D + lane] = (e0 * loc[c] + e1 * fun[c] + e2 * x[c]) * inv;
    }
}

extern "C" void kernel_launch(void* const* d_in, const int* in_sizes, int n_in,
                              void* d_out, int out_size) {
    const float* states = (const float*)d_in[0];
    const int*   nbr    = (const int*)  d_in[1];
    const int*   tiers  = (const int*)  d_in[2];
    const float* W_loc  = (const float*)d_in[3];
    const float* b_loc  = (const float*)d_in[4];
    const float* W_msg  = (const float*)d_in[5];
    const float* b_msg  = (const float*)d_in[6];
    const float* W_fun  = (const float*)d_in[7];
    const float* b_fun  = (const float*)d_in[8];
    const float* W_cnf  = (const float*)d_in[9];
    const float* b_cnf  = (const float*)d_in[10];
    const float* W_gate = (const float*)d_in[11];
    const float* b_gate = (const float*)d_in[12];
    float* out = (float*)d_out;

    const int n = in_sizes[0] / D;
    const int blocks = (n + WPB * CPW - 1) / (WPB * CPW);

    // dynamic smem: 3 weight arrays + input staging + CNF x staging
    const int smem_bytes = (3 * 16 * 32) * (int)sizeof(float4)
                         + (WPB * CPW * D) * (int)sizeof(float4)
                         + (WPB * CPW * XSTR) * (int)sizeof(float);
    static bool attr_set = false;
    if (!attr_set) {
        cudaFuncSetAttribute(moe_main, cudaFuncAttributeMaxDynamicSharedMemorySize, smem_bytes);
        attr_set = true;
    }

    msg_prepass<<<blocks, TPB>>>(n, states, W_msg, b_msg);
    moe_main<<<blocks, TPB, smem_bytes>>>(n, states, nbr, tiers,
                                          W_loc, b_loc, W_fun, b_fun,
                                          W_cnf, b_cnf, W_gate, b_gate, out);
}

// round 9
// speedup vs baseline: 1.4120x; 1.0193x over previous
#include <cuda_runtime.h>

#define D    32
#define KN   26
#define CPW  8               // cells per warp (weight reads amortized 8x)
#define WPB  12              // warps per block
#define TPB  (WPB * 32)
#define NMAX 125000
#define XSTR 36              // x staging row stride (floats)

__device__ float g_msg[NMAX * D];   // precomputed tanh(state @ W_msg + b_msg)

__device__ __forceinline__ float tanh_fast(float x) {
    float y;
    asm("tanh.approx.f32 %0, %1;" : "=f"(y) : "f"(x));
    return y;
}

// ---------------------------------------------------------------------------
// Prepass: g_msg[cell] = tanh(states[cell] @ W_msg + b_msg)
// ---------------------------------------------------------------------------
__global__ __launch_bounds__(384) void msg_prepass(
    int n, const float* __restrict__ states,
    const float* __restrict__ W_msg, const float* __restrict__ b_msg)
{
    __shared__ float sx[12][4 * XSTR];
    const int lane = threadIdx.x & 31, warp = threadIdx.x >> 5;
    const int base = (blockIdx.x * 12 + warp) * 4;
    if (base >= n) return;

    float wm[D];
#pragma unroll
    for (int i = 0; i < D; i++) wm[i] = __ldg(W_msg + i * D + lane);
    const float bm = __ldg(b_msg + lane);

    float* xb = sx[warp];
#pragma unroll
    for (int c = 0; c < 4; c++) {
        int cell = base + c;
        xb[c * XSTR + lane] = (cell < n) ? states[cell * D + lane] : 0.f;
    }
    __syncwarp();
#pragma unroll
    for (int c = 0; c < 4; c++) {
        int cell = base + c;
        float m = bm;
#pragma unroll
        for (int i8 = 0; i8 < 8; i8++) {
            float4 xv = *reinterpret_cast<const float4*>(xb + c * XSTR + 4 * i8);
            m = fmaf(xv.x, wm[4 * i8 + 0], m);
            m = fmaf(xv.y, wm[4 * i8 + 1], m);
            m = fmaf(xv.z, wm[4 * i8 + 2], m);
            m = fmaf(xv.w, wm[4 * i8 + 3], m);
        }
        if (cell < n) g_msg[cell * D + lane] = tanh_fast(m);
    }
}

// ---------------------------------------------------------------------------
// Main kernel: 8 cells/warp, eager gate, sIn-reuse CNF staging
// ---------------------------------------------------------------------------
__global__ __launch_bounds__(TPB, 3) void moe_main(
    int n,
    const float* __restrict__ states,
    const int*   __restrict__ nbr,
    const int*   __restrict__ tiers,
    const float* __restrict__ W_loc,  const float* __restrict__ b_loc,
    const float* __restrict__ W_fun,  const float* __restrict__ b_fun,
    const float* __restrict__ W_cnf,  const float* __restrict__ b_cnf,
    const float* __restrict__ W_gate, const float* __restrict__ b_gate,
    float* __restrict__ out)
{
    extern __shared__ char smem[];
    float4* sWloc4 = reinterpret_cast<float4*>(smem);                 // 16*32
    float4* sWfun4 = sWloc4 + 16 * 32;
    float4* sWcnf4 = sWfun4 + 16 * 32;
    float4* sInAll = sWcnf4 + 16 * 32;                                // WPB*CPW*32 float4
    float4* sGate  = sInAll + WPB * CPW * D;                          // WPB*CPW

    for (int e = threadIdx.x; e < 16 * 32; e += TPB) {
        int i = (e >> 5) * 4, j = e & 31;
        sWloc4[e] = make_float4(W_loc[i * 32 + j], W_loc[(i + 1) * 32 + j],
                                W_loc[(i + 2) * 32 + j], W_loc[(i + 3) * 32 + j]);
        sWfun4[e] = make_float4(W_fun[i * 32 + j], W_fun[(i + 1) * 32 + j],
                                W_fun[(i + 2) * 32 + j], W_fun[(i + 3) * 32 + j]);
        sWcnf4[e] = make_float4(W_cnf[i * 32 + j], W_cnf[(i + 1) * 32 + j],
                                W_cnf[(i + 2) * 32 + j], W_cnf[(i + 3) * 32 + j]);
    }
    __syncthreads();

    const int lane = threadIdx.x & 31, warp = threadIdx.x >> 5;
    const int base = (blockIdx.x * WPB + warp) * CPW;
    if (base >= n) return;
    const unsigned FULL = 0xffffffffu;

    const char* sb = (const char*)states + lane * 4;
    const char* mb = (const char*)g_msg  + lane * 4;

    float4* inb = sInAll + warp * (CPW * D);
    float4* gwp = sGate  + warp * CPW;

    // gate params (used inside gather loop)
    float wg[4][3];
#pragma unroll
    for (int s = 0; s < 4; s++)
#pragma unroll
        for (int e = 0; e < 3; e++)
            wg[s][e] = __ldg(W_gate + (s * D + lane) * 3 + e);
    const float bg0 = __ldg(b_gate + 0), bg1 = __ldg(b_gate + 1), bg2 = __ldg(b_gate + 2);

    // ---- gather + tier means + EAGER gate (all inputs live in regs here) ----
#pragma unroll
    for (int c = 0; c < CPW; c++) {
        const int cell = base + c;
        const bool act = (cell < n);

        float cu = act ? states[cell * D + lane] : 0.f;
        int mypk = 3, myt = 3;
        if (act && lane < KN) {
            int idx = __ldg(nbr   + cell * KN + lane);
            myt     = __ldg(tiers + cell * KN + lane);
            mypk    = idx * 128 + myt;
        }
        const unsigned mask0 = __ballot_sync(FULL, myt == 0);
        const unsigned mask1 = __ballot_sync(FULL, myt == 1);
        const float n0 = (float)__popc(mask0);
        const float n1 = (float)__popc(mask1);
        const float n2 = act ? (float)(KN) - n0 - n1 : 0.f;

        float a0 = 0.f, a1 = 0.f, tot = 0.f, fm = 0.f;
#pragma unroll
        for (int k = 0; k < KN; k++) {
            const int pk  = __shfl_sync(FULL, mypk, k);
            const int t   = pk & 3;
            const long off = (long)(pk & ~127);
            const float v = __ldcg((const float*)(sb + off));
            float mv;
            asm("{ .reg .pred p;\n\t"
                "  setp.eq.s32 p, %1, 1;\n\t"
                "  mov.f32 %0, 0f00000000;\n\t"
                "  @p ld.global.cg.f32 %0, [%2];\n\t"
                "}" : "=f"(mv) : "r"(t), "l"(mb + off));
            tot += v;
            a0  += (t == 0) ? v : 0.f;
            a1  += (t == 1) ? v : 0.f;
            fm  += mv;
        }
        float a2 = tot - a0 - a1;

        a0 = __fdividef(a0, fmaxf(n0, 1.f));
        a1 = __fdividef(a1, fmaxf(n1, 1.f));
        a2 = __fdividef(a2, fmaxf(n2, 1.f));
        fm = __fdividef(fm, fmaxf(n1, 1.f));

        inb[c * D + lane] = make_float4(cu, a0, fm, a2);

        // gate: softmax([cur;a0;a1;a2] @ W_gate + b) -- all inputs in regs
        float p0 = cu * wg[0][0] + a0 * wg[1][0] + a1 * wg[2][0] + a2 * wg[3][0];
        float p1 = cu * wg[0][1] + a0 * wg[1][1] + a1 * wg[2][1] + a2 * wg[3][1];
        float p2 = cu * wg[0][2] + a0 * wg[1][2] + a1 * wg[2][2] + a2 * wg[3][2];
#pragma unroll
        for (int o = 16; o > 0; o >>= 1) {
            p0 += __shfl_xor_sync(FULL, p0, o);
            p1 += __shfl_xor_sync(FULL, p1, o);
            p2 += __shfl_xor_sync(FULL, p2, o);
        }
        if (lane == 0) {
            const float g0 = p0 + bg0, g1 = p1 + bg1, g2 = p2 + bg2;
            const float mx = fmaxf(g0, fmaxf(g1, g2));
            const float e0 = __expf(g0 - mx), e1 = __expf(g1 - mx), e2 = __expf(g2 - mx);
            const float inv = __fdividef(1.f, e0 + e1 + e2);
            gwp[c] = make_float4(e0 * inv, e1 * inv, e2 * inv, 0.f);
        }
    }
    __syncwarp();

    // ---- fused pass: loc, fun, CNF cond half; weights amortized over 8 cells ----
    float accL[CPW], accF[CPW], h2[CPW];
    {
        const float bl = __ldg(b_loc + lane);
        const float bf = __ldg(b_fun + lane);
        const float bc = __ldg(b_cnf + lane);
#pragma unroll
        for (int c = 0; c < CPW; c++) { accL[c] = bl; accF[c] = bf; h2[c] = bc; }
    }

#pragma unroll
    for (int i4 = 0; i4 < 8; i4++) {
        const float4 wlT = sWloc4[i4 * 32 + lane];
        const float4 wlB = sWloc4[(i4 + 8) * 32 + lane];
        const float4 wfT = sWfun4[i4 * 32 + lane];
        const float4 wfB = sWfun4[(i4 + 8) * 32 + lane];
        const float4 wcB = sWcnf4[(i4 + 8) * 32 + lane];
#pragma unroll
        for (int c = 0; c < CPW; c++) {
            const float4 x0 = inb[c * D + 4 * i4 + 0];
            const float4 x1 = inb[c * D + 4 * i4 + 1];
            const float4 x2 = inb[c * D + 4 * i4 + 2];
            const float4 x3 = inb[c * D + 4 * i4 + 3];
            accL[c] = fmaf(x0.x, wlT.x, fmaf(x0.y, wlB.x, accL[c]));
            accL[c] = fmaf(x1.x, wlT.y, fmaf(x1.y, wlB.y, accL[c]));
            accL[c] = fmaf(x2.x, wlT.z, fmaf(x2.y, wlB.z, accL[c]));
            accL[c] = fmaf(x3.x, wlT.w, fmaf(x3.y, wlB.w, accL[c]));
            accF[c] = fmaf(x0.x, wfT.x, fmaf(x0.z, wfB.x, accF[c]));
            accF[c] = fmaf(x1.x, wfT.y, fmaf(x1.z, wfB.y, accF[c]));
            accF[c] = fmaf(x2.x, wfT.z, fmaf(x2.z, wfB.z, accF[c]));
            accF[c] = fmaf(x3.x, wfT.w, fmaf(x3.z, wfB.w, accF[c]));
            h2[c]   = fmaf(x0.w, wcB.x, h2[c]);
            h2[c]   = fmaf(x1.w, wcB.y, h2[c]);
            h2[c]   = fmaf(x2.w, wcB.z, h2[c]);
            h2[c]   = fmaf(x3.w, wcB.w, h2[c]);
        }
    }

    // ---- partial combine (frees accL/accF), init CNF state ----
    float opart[CPW], gw2[CPW], x[CPW];
#pragma unroll
    for (int c = 0; c < CPW; c++) {
        const float4 gwv = gwp[c];                       // uniform LDS.128
        opart[c] = gwv.x * tanh_fast(accL[c]) + gwv.y * tanh_fast(accF[c]);
        gw2[c]   = gwv.z;
        x[c]     = inb[c * D + lane].x;                  // cur
    }
    __syncwarp();

    // ---- CNF: 3 Euler steps; x staged into the now-dead sIn region ----
    float* xxb = reinterpret_cast<float*>(inb);          // reuse: all sIn dead
#pragma unroll
    for (int s = 0; s < 3; s++) {
        __syncwarp();
#pragma unroll
        for (int c = 0; c < CPW; c++) xxb[c * XSTR + lane] = x[c];
        __syncwarp();
        float acc[CPW];
#pragma unroll
        for (int c = 0; c < CPW; c++) acc[c] = h2[c];
#pragma unroll
        for (int i4 = 0; i4 < 8; i4++) {
            const float4 w = sWcnf4[i4 * 32 + lane];
#pragma unroll
            for (int c = 0; c < CPW; c++) {
                const float4 xv = *reinterpret_cast<const float4*>(xxb + c * XSTR + 4 * i4);
                acc[c] = fmaf(xv.x, w.x, fmaf(xv.y, w.y, fmaf(xv.z, w.z, fmaf(xv.w, w.w, acc[c]))));
            }
        }
#pragma unroll
        for (int c = 0; c < CPW; c++)
            x[c] = fmaf(1.0f / 3.0f, tanh_fast(acc[c]), x[c]);
    }

    // ---- final combine + store ----
#pragma unroll
    for (int c = 0; c < CPW; c++) {
        const int cell = base + c;
        if (cell < n)
            out[cell * D + lane] = opart[c] + gw2[c] * x[c];
    }
}

extern "C" void kernel_launch(void* const* d_in, const int* in_sizes, int n_in,
                              void* d_out, int out_size) {
    const float* states = (const float*)d_in[0];
    const int*   nbr    = (const int*)  d_in[1];
    const int*   tiers  = (const int*)  d_in[2];
    const float* W_loc  = (const float*)d_in[3];
    const float* b_loc  = (const float*)d_in[4];
    const float* W_msg  = (const float*)d_in[5];
    const float* b_msg  = (const float*)d_in[6];
    const float* W_fun  = (const float*)d_in[7];
    const float* b_fun  = (const float*)d_in[8];
    const float* W_cnf  = (const float*)d_in[9];
    const float* b_cnf  = (const float*)d_in[10];
    const float* W_gate = (const float*)d_in[11];
    const float* b_gate = (const float*)d_in[12];
    float* out = (float*)d_out;

    const int n = in_sizes[0] / D;
    const int blocksP = (n + 12 * 4 - 1) / (12 * 4);
    const int blocks  = (n + WPB * CPW - 1) / (WPB * CPW);

    // smem: weights 24 KB + sIn 48 KB + sGate 1.5 KB = 73.5 KB -> 3 blocks/SM
    const int smem_bytes = (3 * 16 * 32) * (int)sizeof(float4)
                         + (WPB * CPW * D) * (int)sizeof(float4)
                         + (WPB * CPW) * (int)sizeof(float4);
    static bool attr_set = false;
    if (!attr_set) {
        cudaFuncSetAttribute(moe_main, cudaFuncAttributeMaxDynamicSharedMemorySize, smem_bytes);
        attr_set = true;
    }

    msg_prepass<<<blocksP, 384>>>(n, states, W_msg, b_msg);
    moe_main<<<blocks, TPB, smem_bytes>>>(n, states, nbr, tiers,
                                          W_loc, b_loc, W_fun, b_fun,
                                          W_cnf, b_cnf, W_gate, b_gate, out);
}